// round 16
// baseline (speedup 1.0000x reference)
#include <cuda_runtime.h>
#include <cuda_fp16.h>
#include <math.h>

#define BB 2
#define CC 128
#define LL 56
#define PL 3136      // 56*56
#define SP 175616    // 56^3
#define SPQ 43904    // SP/4 (quads)
#define SLEN 512     // 8*8*8 pooled spatial

// Scratch (static device globals; no allocation)
__device__ __align__(16) float g_sax0[BB][CC][LL];     // d-axis means (complete)
__device__ __align__(16) float g_shp[BB * CC][8][LL];  // h-axis partials (8 chunks)
__device__ __align__(16) float g_swp[BB * CC][8][LL];  // w-axis partials (8 chunks)
__device__ __align__(16) float g_gate[3][BB][CC][LL];  // sigmoid gates
__device__ __align__(16) float g_y[BB][CC][SLEN];      // pooled tensor
__device__ double g_part[BB * CC * 8][2];              // per-(bc,dd) (sum,sumsq)
__device__ __align__(16) float g_gram[BB][8][8][16][16]; // raw Syy partials
__device__ float g_ca[BB][CC];                         // channel attention
__device__ __align__(128) uint2 g_xh[(size_t)BB * CC * SPQ]; // fp16 copy of x (~88MB, < L2)

__device__ __forceinline__ void pdl_wait() {
    asm volatile("griddepcontrol.wait;" ::: "memory");
}

__device__ __forceinline__ float hsum4(float4 v) {
    return (v.x + v.y) + (v.z + v.w);
}

__device__ __forceinline__ uint2 f4_to_h4(float4 v) {
    __half2 h0 = __floats2half2_rn(v.x, v.y);
    __half2 h1 = __floats2half2_rn(v.z, v.w);
    uint2 u;
    u.x = *reinterpret_cast<unsigned*>(&h0);
    u.y = *reinterpret_cast<unsigned*>(&h1);
    return u;
}

__device__ __forceinline__ float4 h4_to_f4(uint2 u) {
    __half2 h0 = *reinterpret_cast<__half2*>(&u.x);
    __half2 h1 = *reinterpret_cast<__half2*>(&u.y);
    float2 f0 = __half22float2(h0);
    float2 f1 = __half22float2(h1);
    return make_float4(f0.x, f0.y, f1.x, f1.y);
}

// ---------------------------------------------------------------------------
// K1: axis-mean partials + fp16 staging of x. grid = bc*8+dd (2048 blocks,
// 7 planes each). blockDim 416 (act t<392), 3 blocks/SM (39 warps).
// ---------------------------------------------------------------------------
__global__ void __launch_bounds__(416, 3) k1_axis_means(const float* __restrict__ x) {
    int id = blockIdx.x;
    int dd = id & 7;
    int bc = id >> 3;
    size_t qbase = (size_t)bc * SPQ + (size_t)dd * 7 * 784;
    const float4* xp = reinterpret_cast<const float4*>(x) + qbase;
    uint2* hx = g_xh + qbase;

    __shared__ float sdp[13][7];      // warp x plane partials
    __shared__ float shq[56][14];     // per-(h,q) sums
    __shared__ float4 swq[28][14];    // per-(R0,q) float4 sums

    int t = threadIdx.x;
    bool act = t < 392;
    int q = t % 14, R0 = t / 14;
    int wid = t >> 5, lane = t & 31;

    float4 v[7];
    float pd[7];
    float h1 = 0.f, h2 = 0.f;
    float4 aw = {0, 0, 0, 0};
    float4 z = {0, 0, 0, 0};

    // batch A: planes 0-6, row R0
#pragma unroll
    for (int i = 0; i < 7; ++i) v[i] = act ? __ldcs(&xp[i * 784 + R0 * 14 + q]) : z;
#pragma unroll
    for (int i = 0; i < 7; ++i) {
        float s = hsum4(v[i]);
        pd[i] = s;
        h1 += s;
        aw.x += v[i].x; aw.y += v[i].y; aw.z += v[i].z; aw.w += v[i].w;
    }
    if (act) {
#pragma unroll
        for (int i = 0; i < 7; ++i) hx[i * 784 + R0 * 14 + q] = f4_to_h4(v[i]);
    }
    // batch B: planes 0-6, row R0+28
#pragma unroll
    for (int i = 0; i < 7; ++i) v[i] = act ? __ldcs(&xp[i * 784 + (R0 + 28) * 14 + q]) : z;
#pragma unroll
    for (int i = 0; i < 7; ++i) {
        float s = hsum4(v[i]);
        pd[i] += s;
        h2 += s;
        aw.x += v[i].x; aw.y += v[i].y; aw.z += v[i].z; aw.w += v[i].w;
    }
    if (act) {
#pragma unroll
        for (int i = 0; i < 7; ++i) hx[i * 784 + (R0 + 28) * 14 + q] = f4_to_h4(v[i]);
    }
    // plane-sum shuffle reductions
#pragma unroll
    for (int i = 0; i < 7; ++i) {
        float s = pd[i];
#pragma unroll
        for (int o = 16; o; o >>= 1) s += __shfl_down_sync(0xffffffffu, s, o);
        if (lane == 0) sdp[wid][i] = s;
    }
    if (act) {
        shq[R0][q] = h1;
        shq[R0 + 28][q] = h2;
        swq[R0][q] = aw;
    }
    __syncthreads();

    int b = bc >> 7, c = bc & 127;
    if (t < 7) {
        float s = 0.f;
#pragma unroll
        for (int w = 0; w < 13; ++w) s += sdp[w][t];
        g_sax0[b][c][dd * 7 + t] = s * (1.0f / (float)PL);
    } else if (t >= 64 && t < 64 + LL) {
        int h = t - 64;
        float s = 0.f;
#pragma unroll
        for (int j = 0; j < 14; ++j) s += shq[h][j];
        g_shp[bc][dd][h] = s;
    } else if (t >= 128 && t < 128 + LL) {
        int w = t - 128;
        int qq = w >> 2, comp = w & 3;
        float s = 0.f;
#pragma unroll
        for (int r = 0; r < 28; ++r) {
            const float* p = reinterpret_cast<const float*>(&swq[r][qq]);
            s += p[comp];
        }
        g_swp[bc][dd][w] = s;
    }
}

// ---------------------------------------------------------------------------
// K2: combine 8 partial chunks + depthwise conv + GroupNorm(4) + sigmoid.
// grid = 24, PDL wait on k1.
// ---------------------------------------------------------------------------
__global__ void k2_gates(const float* __restrict__ wl, const float* __restrict__ bl,
                         const float* __restrict__ ws, const float* __restrict__ bs,
                         const float* __restrict__ wm, const float* __restrict__ bm,
                         const float* __restrict__ wg, const float* __restrict__ bg,
                         const float* __restrict__ gd, const float* __restrict__ btd,
                         const float* __restrict__ gh, const float* __restrict__ bth,
                         const float* __restrict__ gw, const float* __restrict__ btw) {
    pdl_wait();
    int idx = blockIdx.x;
    int axis = idx >> 3;
    int b = (idx >> 2) & 1;
    int g = idx & 3;
    const int ksz[4] = {3, 5, 7, 9};
    const float* wptr[4] = {wl, ws, wm, wg};
    const float* bptr[4] = {bl, bs, bm, bg};
    const float* gam[3] = {gd, gh, gw};
    const float* bet[3] = {btd, bth, btw};
    int k = ksz[g], half = k >> 1;

    __shared__ float s_in[32][LL];
    __shared__ float s_out[32][LL];
    __shared__ float s_w[32 * 9];
    __shared__ float s_b[32];
    __shared__ float red[2];
    __shared__ float rs[8], rq[8];

    int tid = threadIdx.x;
    for (int i = tid; i < 32 * LL; i += 256) {
        int cc = i / LL, l = i % LL;
        int c = g * 32 + cc;
        float v;
        if (axis == 0) {
            v = g_sax0[b][c][l];
        } else {
            int bcc = b * 128 + c;
            const float(*pp)[8][LL] = (axis == 1) ? g_shp : g_swp;
            float s = 0.f;
#pragma unroll
            for (int p = 0; p < 8; ++p) s += pp[bcc][p][l];
            v = s * (1.0f / (float)PL);
        }
        s_in[cc][l] = v;
    }
    for (int i = tid; i < 32 * k; i += 256) s_w[i] = wptr[g][i];
    if (tid < 32) s_b[tid] = bptr[g][tid];
    __syncthreads();

    float lsum = 0.f, lsq = 0.f;
    for (int i = tid; i < 32 * LL; i += 256) {
        int cc = i / LL, l = i % LL;
        float acc = s_b[cc];
        for (int j = 0; j < k; ++j) {
            int p = l + j - half;
            if (p >= 0 && p < LL) acc += s_w[cc * k + j] * s_in[cc][p];
        }
        s_out[cc][l] = acc;
        lsum += acc;
        lsq += acc * acc;
    }
#pragma unroll
    for (int o = 16; o; o >>= 1) {
        lsum += __shfl_down_sync(0xffffffffu, lsum, o);
        lsq  += __shfl_down_sync(0xffffffffu, lsq, o);
    }
    if ((tid & 31) == 0) { rs[tid >> 5] = lsum; rq[tid >> 5] = lsq; }
    __syncthreads();
    if (tid == 0) {
        float S = 0.f, Q = 0.f;
        for (int i = 0; i < 8; ++i) { S += rs[i]; Q += rq[i]; }
        float n = 32.f * LL;
        float mu = S / n;
        float var = Q / n - mu * mu;
        red[0] = mu;
        red[1] = rsqrtf(var + 1e-5f);
    }
    __syncthreads();
    float mu = red[0], rstd = red[1];
    for (int i = tid; i < 32 * LL; i += 256) {
        int cc = i / LL, l = i % LL;
        int c = g * 32 + cc;
        float v = (s_out[cc][l] - mu) * rstd * gam[axis][c] + bet[axis][c];
        g_gate[axis][b][c][l] = 1.f / (1.f + expf(-v));
    }
}

// ---------------------------------------------------------------------------
// K3: pool gated x (fp16 copy) into y. 2 units/block with simple prefetch.
// grid = bc*4+pair (1024), blockDim 416, 3 blocks/SM.
// ---------------------------------------------------------------------------
__global__ void __launch_bounds__(416, 3) k3_pool() {
    pdl_wait();
    int id = blockIdx.x;
    int pair = id & 3;
    int bc = id >> 2;
    int b = bc >> 7, c = bc & 127;
    const uint2* xp = g_xh + (size_t)bc * SPQ + (size_t)pair * 14 * 784;

    __shared__ float sgd[14], sgh[LL], sgw[LL];
    __shared__ float4 sacc[56][14];
    __shared__ double pr[2][2];

    int t = threadIdx.x;
    bool act = t < 392;
    int q = t % 14, R0 = t / 14;

    if (t < LL) { sgh[t] = g_gate[1][b][c][t]; sgw[t] = g_gate[2][b][c][t]; }
    if (t >= 64 && t < 78) sgd[t - 64] = g_gate[0][b][c][pair * 14 + (t - 64)];
    __syncthreads();

    uint2 u[7];
    // ---- unit 0 (planes 0-6) ----
    if (act) {
        float4 a1 = {0, 0, 0, 0}, a2 = {0, 0, 0, 0};
#pragma unroll
        for (int i = 0; i < 7; ++i) u[i] = __ldcg(&xp[i * 784 + R0 * 14 + q]);
#pragma unroll
        for (int i = 0; i < 7; ++i) {
            float g = sgd[i];
            float4 v = h4_to_f4(u[i]);
            a1.x += g * v.x; a1.y += g * v.y; a1.z += g * v.z; a1.w += g * v.w;
        }
#pragma unroll
        for (int i = 0; i < 7; ++i) u[i] = __ldcg(&xp[i * 784 + (R0 + 28) * 14 + q]);
#pragma unroll
        for (int i = 0; i < 7; ++i) {
            float g = sgd[i];
            float4 v = h4_to_f4(u[i]);
            a2.x += g * v.x; a2.y += g * v.y; a2.z += g * v.z; a2.w += g * v.w;
        }
        sacc[R0][q] = a1;
        sacc[R0 + 28][q] = a2;
        // prefetch unit 1 batch 1
#pragma unroll
        for (int i = 0; i < 7; ++i) u[i] = __ldcg(&xp[(7 + i) * 784 + R0 * 14 + q]);
    }
    __syncthreads();

    if (t < 64) {
        int hh = t >> 3, ww = t & 7;
        float s = 0.f;
#pragma unroll
        for (int ih = 0; ih < 7; ++ih) {
            int h = hh * 7 + ih;
            float inner = 0.f;
#pragma unroll
            for (int iw = 0; iw < 7; ++iw) {
                int w = ww * 7 + iw;
                const float* p = reinterpret_cast<const float*>(&sacc[h][w >> 2]);
                inner += p[w & 3] * sgw[w];
            }
            s += inner * sgh[h];
        }
        float yv = s * (1.0f / 343.0f);
        g_y[b][c][(pair * 2) * 64 + hh * 8 + ww] = yv;
        double sv = yv, sq = (double)yv * yv;
#pragma unroll
        for (int o = 16; o; o >>= 1) {
            sv += __shfl_down_sync(0xffffffffu, sv, o);
            sq += __shfl_down_sync(0xffffffffu, sq, o);
        }
        if ((t & 31) == 0) { pr[t >> 5][0] = sv; pr[t >> 5][1] = sq; }
    }
    __syncthreads();
    if (t == 0) {
        g_part[bc * 8 + pair * 2][0] = pr[0][0] + pr[1][0];
        g_part[bc * 8 + pair * 2][1] = pr[0][1] + pr[1][1];
    }

    // ---- unit 1 (planes 7-13) ----
    if (act) {
        float4 a1 = {0, 0, 0, 0}, a2 = {0, 0, 0, 0};
#pragma unroll
        for (int i = 0; i < 7; ++i) {
            float g = sgd[7 + i];
            float4 v = h4_to_f4(u[i]);
            a1.x += g * v.x; a1.y += g * v.y; a1.z += g * v.z; a1.w += g * v.w;
        }
#pragma unroll
        for (int i = 0; i < 7; ++i) u[i] = __ldcg(&xp[(7 + i) * 784 + (R0 + 28) * 14 + q]);
#pragma unroll
        for (int i = 0; i < 7; ++i) {
            float g = sgd[7 + i];
            float4 v = h4_to_f4(u[i]);
            a2.x += g * v.x; a2.y += g * v.y; a2.z += g * v.z; a2.w += g * v.w;
        }
        sacc[R0][q] = a1;
        sacc[R0 + 28][q] = a2;
    }
    __syncthreads();

    if (t < 64) {
        int hh = t >> 3, ww = t & 7;
        float s = 0.f;
#pragma unroll
        for (int ih = 0; ih < 7; ++ih) {
            int h = hh * 7 + ih;
            float inner = 0.f;
#pragma unroll
            for (int iw = 0; iw < 7; ++iw) {
                int w = ww * 7 + iw;
                const float* p = reinterpret_cast<const float*>(&sacc[h][w >> 2]);
                inner += p[w & 3] * sgw[w];
            }
            s += inner * sgh[h];
        }
        float yv = s * (1.0f / 343.0f);
        g_y[b][c][(pair * 2 + 1) * 64 + hh * 8 + ww] = yv;
        double sv = yv, sq = (double)yv * yv;
#pragma unroll
        for (int o = 16; o; o >>= 1) {
            sv += __shfl_down_sync(0xffffffffu, sv, o);
            sq += __shfl_down_sync(0xffffffffu, sq, o);
        }
        if ((t & 31) == 0) { pr[t >> 5][0] = sv; pr[t >> 5][1] = sq; }
    }
    __syncthreads();
    if (t == 0) {
        g_part[bc * 8 + pair * 2 + 1][0] = pr[0][0] + pr[1][0];
        g_part[bc * 8 + pair * 2 + 1][1] = pr[0][1] + pr[1][1];
    }
}

// ---------------------------------------------------------------------------
// K3b: raw Gram partials Syy over 64-s chunks. grid = 128, 256 threads.
// ---------------------------------------------------------------------------
__global__ void k3b_gram() {
    pdl_wait();
    int id = blockIdx.x;
    int sc = id & 7;
    int head = (id >> 3) & 7;
    int b = id >> 6;
    __shared__ float sy[16][68];
    int tid = threadIdx.x;
    {
        int row = tid >> 4, c4 = (tid & 15) * 4;
        float4 v = *reinterpret_cast<const float4*>(&g_y[b][head * 16 + row][sc * 64 + c4]);
        sy[row][c4] = v.x; sy[row][c4 + 1] = v.y;
        sy[row][c4 + 2] = v.z; sy[row][c4 + 3] = v.w;
    }
    __syncthreads();
    int i = tid >> 4, j = tid & 15;
    float a0 = 0.f, a1 = 0.f, a2 = 0.f, a3 = 0.f;
#pragma unroll
    for (int s = 0; s < 64; s += 4) {
        a0 += sy[i][s] * sy[j][s];
        a1 += sy[i][s + 1] * sy[j][s + 1];
        a2 += sy[i][s + 2] * sy[j][s + 2];
        a3 += sy[i][s + 3] * sy[j][s + 3];
    }
    g_gram[b][head][sc][i][j] = (a0 + a1) + (a2 + a3);
}

// ---------------------------------------------------------------------------
// K4: stats + combine Syy + channel attention (affine identity). grid=16.
// ---------------------------------------------------------------------------
__global__ void k4_attn(const float* __restrict__ gn, const float* __restrict__ btn,
                        const float* __restrict__ wq, const float* __restrict__ wk,
                        const float* __restrict__ wv) {
    pdl_wait();
    int b = blockIdx.x >> 3;
    int head = blockIdx.x & 7;
    int c0 = head * 16;
    int tid = threadIdx.x;
    __shared__ double rs[8], rq[8];
    __shared__ float stat[2];
    __shared__ float Syy[16][16];
    __shared__ float Sy[16];

    double s = 0.0, q = 0.0;
    for (int i = tid; i < 1024; i += 256) {
        s += g_part[b * 1024 + i][0];
        q += g_part[b * 1024 + i][1];
    }
#pragma unroll
    for (int o = 16; o; o >>= 1) {
        s += __shfl_down_sync(0xffffffffu, s, o);
        q += __shfl_down_sync(0xffffffffu, q, o);
    }
    if ((tid & 31) == 0) { rs[tid >> 5] = s; rq[tid >> 5] = q; }

    {
        int i = tid >> 4, j = tid & 15;
        float a = 0.f;
#pragma unroll
        for (int sc = 0; sc < 8; ++sc) a += g_gram[b][head][sc][i][j];
        Syy[i][j] = a;
    }
    if (tid < 16) {
        double a = 0.0;
#pragma unroll
        for (int dd = 0; dd < 8; ++dd) a += g_part[(b * 128 + c0 + tid) * 8 + dd][0];
        Sy[tid] = (float)a;
    }
    __syncthreads();
    if (tid == 0) {
        double S = 0.0, Q = 0.0;
        for (int i = 0; i < 8; ++i) { S += rs[i]; Q += rq[i]; }
        double n = (double)(CC * SLEN);
        double mu = S / n;
        double var = Q / n - mu * mu;
        stat[0] = (float)mu;
        stat[1] = (float)(1.0 / sqrt(var + 1e-5));
    }
    __syncthreads();

    if (tid < 16) {
        double mu = stat[0], rstd = stat[1];
        int i = tid;
        double ai = rstd * (double)gn[c0 + i];
        double bi = (double)btn[c0 + i] - mu * ai;
        double qi = (double)wq[c0 + i] * 0.25;  // includes HD^-0.5
        double sc_[16], vm[16];
        double m = -1e300;
#pragma unroll
        for (int j = 0; j < 16; ++j) {
            double aj = rstd * (double)gn[c0 + j];
            double bj = (double)btn[c0 + j] - mu * aj;
            double G = ai * aj * (double)Syy[i][j] + ai * bj * (double)Sy[i]
                     + bi * aj * (double)Sy[j] + 512.0 * bi * bj;
            sc_[j] = qi * (double)wk[c0 + j] * G;
            vm[j] = (double)wv[c0 + j] * (aj * (double)Sy[j] + 512.0 * bj) * (1.0 / 512.0);
            if (sc_[j] > m) m = sc_[j];
        }
        double sum = 0.0, o = 0.0;
#pragma unroll
        for (int j = 0; j < 16; ++j) {
            double e = exp(sc_[j] - m);
            sum += e;
            o += e * vm[j];
        }
        o /= sum;
        g_ca[b][c0 + i] = (float)(1.0 / (1.0 + exp(-o)));
    }
}

// ---------------------------------------------------------------------------
// K5: out = xh(fp16, L2-resident) * gd*gh*gw*ca. grid = 2048, blockDim 416,
// 3 blocks/SM. __ldcs reads (last use), __stcs writes; discard L2 region after.
// ---------------------------------------------------------------------------
__global__ void __launch_bounds__(416, 3) k5_gate_out(float* __restrict__ out) {
    pdl_wait();
    int id = blockIdx.x;
    int ch = id & 7;
    int bc = id >> 3;
    int b = bc >> 7, c = bc & 127;
    const uint2* xp = g_xh + (size_t)bc * SPQ;
    float4* op = reinterpret_cast<float4*>(out + (size_t)bc * SP);

    __shared__ float srs[392];
    __shared__ float4 sgw4[14];

    int t = threadIdx.x;
    bool act = t < 392;
    if (act) {
        int dl = t / 56, h = t % 56;
        srs[t] = g_gate[0][b][c][ch * 7 + dl] * g_gate[1][b][c][h] * g_ca[b][c];
    }
    if (t < 14) {
        sgw4[t] = reinterpret_cast<const float4*>(&g_gate[2][b][c][0])[t];
    }
    __syncthreads();

    if (act) {
        int q = t % 14, R0 = t / 14;
        float4 gw = sgw4[q];
        int base = ch * 5488 + R0 * 14 + q;
        uint2 u[7];
#pragma unroll
        for (int half = 0; half < 2; ++half) {
            int m0 = half * 7;
#pragma unroll
            for (int m = 0; m < 7; ++m) u[m] = __ldcs(&xp[base + (m0 + m) * 392]);
#pragma unroll
            for (int m = 0; m < 7; ++m) {
                float sc = srs[R0 + 28 * (m0 + m)];
                float4 v = h4_to_f4(u[m]);
                v.x *= sc * gw.x;
                v.y *= sc * gw.y;
                v.z *= sc * gw.z;
                v.w *= sc * gw.w;
                __stcs(&op[base + (m0 + m) * 392], v);
            }
        }
    }
    __syncthreads();
    // Discard this block's g_xh region: 343 lines of 128B, region aligned.
    {
        const char* rbase = reinterpret_cast<const char*>(xp + ch * 5488);
        for (int l = t; l < 343; l += 416) {
            asm volatile("discard.global.L2 [%0], 128;"
                         :: "l"(rbase + (size_t)l * 128) : "memory");
        }
    }
}

// ---------------------------------------------------------------------------
// Host: launches 2-6 use PDL so each launch overlaps the predecessor's
// teardown; griddepcontrol.wait at kernel entry preserves ordering.
// ---------------------------------------------------------------------------
template <typename F, typename... Args>
static inline void launch_pdl(F f, dim3 grid, dim3 block, Args... args) {
    cudaLaunchConfig_t cfg = {};
    cfg.gridDim = grid;
    cfg.blockDim = block;
    cfg.dynamicSmemBytes = 0;
    cudaLaunchAttribute at[1];
    at[0].id = cudaLaunchAttributeProgrammaticStreamSerialization;
    at[0].val.programmaticStreamSerializationAllowed = 1;
    cfg.attrs = at;
    cfg.numAttrs = 1;
    cudaLaunchKernelEx(&cfg, f, args...);
}

extern "C" void kernel_launch(void* const* d_in, const int* in_sizes, int n_in,
                              void* d_out, int out_size) {
    const float* x = (const float*)d_in[0];
    float* out = (float*)d_out;

    k1_axis_means<<<BB * CC * 8, 416>>>(x);
    launch_pdl(k2_gates, dim3(24), dim3(256),
        (const float*)d_in[1], (const float*)d_in[2],
        (const float*)d_in[3], (const float*)d_in[4],
        (const float*)d_in[5], (const float*)d_in[6],
        (const float*)d_in[7], (const float*)d_in[8],
        (const float*)d_in[9], (const float*)d_in[10],
        (const float*)d_in[11], (const float*)d_in[12],
        (const float*)d_in[13], (const float*)d_in[14]);
    launch_pdl(k3_pool, dim3(BB * CC * 4), dim3(416));
    launch_pdl(k3b_gram, dim3(BB * 64), dim3(256));
    launch_pdl(k4_attn, dim3(BB * 8), dim3(256),
        (const float*)d_in[15], (const float*)d_in[16],
        (const float*)d_in[17], (const float*)d_in[18],
        (const float*)d_in[19]);
    launch_pdl(k5_gate_out, dim3(BB * CC * 8), dim3(416), out);
}

// round 17
// speedup vs baseline: 1.0659x; 1.0659x over previous
#include <cuda_runtime.h>
#include <cuda_fp16.h>
#include <math.h>

#define BB 2
#define CC 128
#define LL 56
#define PL 3136      // 56*56
#define SP 175616    // 56^3
#define SPQ 43904    // SP/4 (quads)
#define SLEN 512     // 8*8*8 pooled spatial

// Scratch (static device globals; no allocation)
__device__ __align__(16) float g_sax0[BB][CC][LL];     // d-axis means (complete)
__device__ __align__(16) float g_shp[BB * CC][8][LL];  // h-axis partials (8 chunks)
__device__ __align__(16) float g_swp[BB * CC][8][LL];  // w-axis partials (8 chunks)
__device__ __align__(16) float g_gate[3][BB][CC][LL];  // sigmoid gates
__device__ __align__(16) float g_y[BB][CC][SLEN];      // pooled tensor
__device__ double g_part[BB * CC * 8][2];              // per-(bc,dd) (sum,sumsq)
__device__ __align__(16) float g_gram[BB][8][8][16][16]; // raw Syy partials
__device__ float g_ca[BB][CC];                         // channel attention
__device__ __align__(128) uint2 g_xh[(size_t)BB * CC * SPQ]; // fp16 copy of x (~88MB, < L2)

__device__ __forceinline__ void pdl_wait() {
    asm volatile("griddepcontrol.wait;" ::: "memory");
}

__device__ __forceinline__ float hsum4(float4 v) {
    return (v.x + v.y) + (v.z + v.w);
}

__device__ __forceinline__ uint2 f4_to_h4(float4 v) {
    __half2 h0 = __floats2half2_rn(v.x, v.y);
    __half2 h1 = __floats2half2_rn(v.z, v.w);
    uint2 u;
    u.x = *reinterpret_cast<unsigned*>(&h0);
    u.y = *reinterpret_cast<unsigned*>(&h1);
    return u;
}

__device__ __forceinline__ float4 h4_to_f4(uint2 u) {
    __half2 h0 = *reinterpret_cast<__half2*>(&u.x);
    __half2 h1 = *reinterpret_cast<__half2*>(&u.y);
    float2 f0 = __half22float2(h0);
    float2 f1 = __half22float2(h1);
    return make_float4(f0.x, f0.y, f1.x, f1.y);
}

// ---------------------------------------------------------------------------
// K1: axis-mean partials + fp16 staging of x. grid = bc*8+dd (2048 blocks,
// 7 planes each). blockDim 416 (act t<392), 2 blocks/SM (no reg squeeze).
// ---------------------------------------------------------------------------
__global__ void __launch_bounds__(416, 2) k1_axis_means(const float* __restrict__ x) {
    int id = blockIdx.x;
    int dd = id & 7;
    int bc = id >> 3;
    size_t qbase = (size_t)bc * SPQ + (size_t)dd * 7 * 784;
    const float4* xp = reinterpret_cast<const float4*>(x) + qbase;
    uint2* hx = g_xh + qbase;

    __shared__ float sdp[13][7];      // warp x plane partials
    __shared__ float shq[56][14];     // per-(h,q) sums
    __shared__ float4 swq[28][14];    // per-(R0,q) float4 sums

    int t = threadIdx.x;
    bool act = t < 392;
    int q = t % 14, R0 = t / 14;
    int wid = t >> 5, lane = t & 31;

    float4 v[7];
    float pd[7];
    float h1 = 0.f, h2 = 0.f;
    float4 aw = {0, 0, 0, 0};
    float4 z = {0, 0, 0, 0};

    // batch A: planes 0-6, row R0
#pragma unroll
    for (int i = 0; i < 7; ++i) v[i] = act ? __ldcs(&xp[i * 784 + R0 * 14 + q]) : z;
#pragma unroll
    for (int i = 0; i < 7; ++i) {
        float s = hsum4(v[i]);
        pd[i] = s;
        h1 += s;
        aw.x += v[i].x; aw.y += v[i].y; aw.z += v[i].z; aw.w += v[i].w;
    }
    if (act) {
#pragma unroll
        for (int i = 0; i < 7; ++i) hx[i * 784 + R0 * 14 + q] = f4_to_h4(v[i]);
    }
    // batch B: planes 0-6, row R0+28
#pragma unroll
    for (int i = 0; i < 7; ++i) v[i] = act ? __ldcs(&xp[i * 784 + (R0 + 28) * 14 + q]) : z;
#pragma unroll
    for (int i = 0; i < 7; ++i) {
        float s = hsum4(v[i]);
        pd[i] += s;
        h2 += s;
        aw.x += v[i].x; aw.y += v[i].y; aw.z += v[i].z; aw.w += v[i].w;
    }
    if (act) {
#pragma unroll
        for (int i = 0; i < 7; ++i) hx[i * 784 + (R0 + 28) * 14 + q] = f4_to_h4(v[i]);
    }
    // plane-sum shuffle reductions
#pragma unroll
    for (int i = 0; i < 7; ++i) {
        float s = pd[i];
#pragma unroll
        for (int o = 16; o; o >>= 1) s += __shfl_down_sync(0xffffffffu, s, o);
        if (lane == 0) sdp[wid][i] = s;
    }
    if (act) {
        shq[R0][q] = h1;
        shq[R0 + 28][q] = h2;
        swq[R0][q] = aw;
    }
    __syncthreads();

    int b = bc >> 7, c = bc & 127;
    if (t < 7) {
        float s = 0.f;
#pragma unroll
        for (int w = 0; w < 13; ++w) s += sdp[w][t];
        g_sax0[b][c][dd * 7 + t] = s * (1.0f / (float)PL);
    } else if (t >= 64 && t < 64 + LL) {
        int h = t - 64;
        float s = 0.f;
#pragma unroll
        for (int j = 0; j < 14; ++j) s += shq[h][j];
        g_shp[bc][dd][h] = s;
    } else if (t >= 128 && t < 128 + LL) {
        int w = t - 128;
        int qq = w >> 2, comp = w & 3;
        float s = 0.f;
#pragma unroll
        for (int r = 0; r < 28; ++r) {
            const float* p = reinterpret_cast<const float*>(&swq[r][qq]);
            s += p[comp];
        }
        g_swp[bc][dd][w] = s;
    }
}

// ---------------------------------------------------------------------------
// K2: combine 8 partial chunks + depthwise conv + GroupNorm(4) + sigmoid.
// grid = 24, PDL wait on k1.
// ---------------------------------------------------------------------------
__global__ void k2_gates(const float* __restrict__ wl, const float* __restrict__ bl,
                         const float* __restrict__ ws, const float* __restrict__ bs,
                         const float* __restrict__ wm, const float* __restrict__ bm,
                         const float* __restrict__ wg, const float* __restrict__ bg,
                         const float* __restrict__ gd, const float* __restrict__ btd,
                         const float* __restrict__ gh, const float* __restrict__ bth,
                         const float* __restrict__ gw, const float* __restrict__ btw) {
    pdl_wait();
    int idx = blockIdx.x;
    int axis = idx >> 3;
    int b = (idx >> 2) & 1;
    int g = idx & 3;
    const int ksz[4] = {3, 5, 7, 9};
    const float* wptr[4] = {wl, ws, wm, wg};
    const float* bptr[4] = {bl, bs, bm, bg};
    const float* gam[3] = {gd, gh, gw};
    const float* bet[3] = {btd, bth, btw};
    int k = ksz[g], half = k >> 1;

    __shared__ float s_in[32][LL];
    __shared__ float s_out[32][LL];
    __shared__ float s_w[32 * 9];
    __shared__ float s_b[32];
    __shared__ float red[2];
    __shared__ float rs[8], rq[8];

    int tid = threadIdx.x;
    for (int i = tid; i < 32 * LL; i += 256) {
        int cc = i / LL, l = i % LL;
        int c = g * 32 + cc;
        float v;
        if (axis == 0) {
            v = g_sax0[b][c][l];
        } else {
            int bcc = b * 128 + c;
            const float(*pp)[8][LL] = (axis == 1) ? g_shp : g_swp;
            float s = 0.f;
#pragma unroll
            for (int p = 0; p < 8; ++p) s += pp[bcc][p][l];
            v = s * (1.0f / (float)PL);
        }
        s_in[cc][l] = v;
    }
    for (int i = tid; i < 32 * k; i += 256) s_w[i] = wptr[g][i];
    if (tid < 32) s_b[tid] = bptr[g][tid];
    __syncthreads();

    float lsum = 0.f, lsq = 0.f;
    for (int i = tid; i < 32 * LL; i += 256) {
        int cc = i / LL, l = i % LL;
        float acc = s_b[cc];
        for (int j = 0; j < k; ++j) {
            int p = l + j - half;
            if (p >= 0 && p < LL) acc += s_w[cc * k + j] * s_in[cc][p];
        }
        s_out[cc][l] = acc;
        lsum += acc;
        lsq += acc * acc;
    }
#pragma unroll
    for (int o = 16; o; o >>= 1) {
        lsum += __shfl_down_sync(0xffffffffu, lsum, o);
        lsq  += __shfl_down_sync(0xffffffffu, lsq, o);
    }
    if ((tid & 31) == 0) { rs[tid >> 5] = lsum; rq[tid >> 5] = lsq; }
    __syncthreads();
    if (tid == 0) {
        float S = 0.f, Q = 0.f;
        for (int i = 0; i < 8; ++i) { S += rs[i]; Q += rq[i]; }
        float n = 32.f * LL;
        float mu = S / n;
        float var = Q / n - mu * mu;
        red[0] = mu;
        red[1] = rsqrtf(var + 1e-5f);
    }
    __syncthreads();
    float mu = red[0], rstd = red[1];
    for (int i = tid; i < 32 * LL; i += 256) {
        int cc = i / LL, l = i % LL;
        int c = g * 32 + cc;
        float v = (s_out[cc][l] - mu) * rstd * gam[axis][c] + bet[axis][c];
        g_gate[axis][b][c][l] = 1.f / (1.f + expf(-v));
    }
}

// ---------------------------------------------------------------------------
// K3: pool gated x (fp16 copy) into y. 2 units/block with simple prefetch.
// grid = bc*4+pair (1024), blockDim 416, 3 blocks/SM (regs fit, no squeeze).
// ---------------------------------------------------------------------------
__global__ void __launch_bounds__(416, 3) k3_pool() {
    pdl_wait();
    int id = blockIdx.x;
    int pair = id & 3;
    int bc = id >> 2;
    int b = bc >> 7, c = bc & 127;
    const uint2* xp = g_xh + (size_t)bc * SPQ + (size_t)pair * 14 * 784;

    __shared__ float sgd[14], sgh[LL], sgw[LL];
    __shared__ float4 sacc[56][14];
    __shared__ double pr[2][2];

    int t = threadIdx.x;
    bool act = t < 392;
    int q = t % 14, R0 = t / 14;

    if (t < LL) { sgh[t] = g_gate[1][b][c][t]; sgw[t] = g_gate[2][b][c][t]; }
    if (t >= 64 && t < 78) sgd[t - 64] = g_gate[0][b][c][pair * 14 + (t - 64)];
    __syncthreads();

    uint2 u[7];
    // ---- unit 0 (planes 0-6) ----
    if (act) {
        float4 a1 = {0, 0, 0, 0}, a2 = {0, 0, 0, 0};
#pragma unroll
        for (int i = 0; i < 7; ++i) u[i] = __ldcg(&xp[i * 784 + R0 * 14 + q]);
#pragma unroll
        for (int i = 0; i < 7; ++i) {
            float g = sgd[i];
            float4 v = h4_to_f4(u[i]);
            a1.x += g * v.x; a1.y += g * v.y; a1.z += g * v.z; a1.w += g * v.w;
        }
#pragma unroll
        for (int i = 0; i < 7; ++i) u[i] = __ldcg(&xp[i * 784 + (R0 + 28) * 14 + q]);
#pragma unroll
        for (int i = 0; i < 7; ++i) {
            float g = sgd[i];
            float4 v = h4_to_f4(u[i]);
            a2.x += g * v.x; a2.y += g * v.y; a2.z += g * v.z; a2.w += g * v.w;
        }
        sacc[R0][q] = a1;
        sacc[R0 + 28][q] = a2;
        // prefetch unit 1 batch 1
#pragma unroll
        for (int i = 0; i < 7; ++i) u[i] = __ldcg(&xp[(7 + i) * 784 + R0 * 14 + q]);
    }
    __syncthreads();

    if (t < 64) {
        int hh = t >> 3, ww = t & 7;
        float s = 0.f;
#pragma unroll
        for (int ih = 0; ih < 7; ++ih) {
            int h = hh * 7 + ih;
            float inner = 0.f;
#pragma unroll
            for (int iw = 0; iw < 7; ++iw) {
                int w = ww * 7 + iw;
                const float* p = reinterpret_cast<const float*>(&sacc[h][w >> 2]);
                inner += p[w & 3] * sgw[w];
            }
            s += inner * sgh[h];
        }
        float yv = s * (1.0f / 343.0f);
        g_y[b][c][(pair * 2) * 64 + hh * 8 + ww] = yv;
        double sv = yv, sq = (double)yv * yv;
#pragma unroll
        for (int o = 16; o; o >>= 1) {
            sv += __shfl_down_sync(0xffffffffu, sv, o);
            sq += __shfl_down_sync(0xffffffffu, sq, o);
        }
        if ((t & 31) == 0) { pr[t >> 5][0] = sv; pr[t >> 5][1] = sq; }
    }
    __syncthreads();
    if (t == 0) {
        g_part[bc * 8 + pair * 2][0] = pr[0][0] + pr[1][0];
        g_part[bc * 8 + pair * 2][1] = pr[0][1] + pr[1][1];
    }

    // ---- unit 1 (planes 7-13) ----
    if (act) {
        float4 a1 = {0, 0, 0, 0}, a2 = {0, 0, 0, 0};
#pragma unroll
        for (int i = 0; i < 7; ++i) {
            float g = sgd[7 + i];
            float4 v = h4_to_f4(u[i]);
            a1.x += g * v.x; a1.y += g * v.y; a1.z += g * v.z; a1.w += g * v.w;
        }
#pragma unroll
        for (int i = 0; i < 7; ++i) u[i] = __ldcg(&xp[(7 + i) * 784 + (R0 + 28) * 14 + q]);
#pragma unroll
        for (int i = 0; i < 7; ++i) {
            float g = sgd[7 + i];
            float4 v = h4_to_f4(u[i]);
            a2.x += g * v.x; a2.y += g * v.y; a2.z += g * v.z; a2.w += g * v.w;
        }
        sacc[R0][q] = a1;
        sacc[R0 + 28][q] = a2;
    }
    __syncthreads();

    if (t < 64) {
        int hh = t >> 3, ww = t & 7;
        float s = 0.f;
#pragma unroll
        for (int ih = 0; ih < 7; ++ih) {
            int h = hh * 7 + ih;
            float inner = 0.f;
#pragma unroll
            for (int iw = 0; iw < 7; ++iw) {
                int w = ww * 7 + iw;
                const float* p = reinterpret_cast<const float*>(&sacc[h][w >> 2]);
                inner += p[w & 3] * sgw[w];
            }
            s += inner * sgh[h];
        }
        float yv = s * (1.0f / 343.0f);
        g_y[b][c][(pair * 2 + 1) * 64 + hh * 8 + ww] = yv;
        double sv = yv, sq = (double)yv * yv;
#pragma unroll
        for (int o = 16; o; o >>= 1) {
            sv += __shfl_down_sync(0xffffffffu, sv, o);
            sq += __shfl_down_sync(0xffffffffu, sq, o);
        }
        if ((t & 31) == 0) { pr[t >> 5][0] = sv; pr[t >> 5][1] = sq; }
    }
    __syncthreads();
    if (t == 0) {
        g_part[bc * 8 + pair * 2 + 1][0] = pr[0][0] + pr[1][0];
        g_part[bc * 8 + pair * 2 + 1][1] = pr[0][1] + pr[1][1];
    }
}

// ---------------------------------------------------------------------------
// K3b: raw Gram partials Syy over 64-s chunks. grid = 128, 256 threads.
// ---------------------------------------------------------------------------
__global__ void k3b_gram() {
    pdl_wait();
    int id = blockIdx.x;
    int sc = id & 7;
    int head = (id >> 3) & 7;
    int b = id >> 6;
    __shared__ float sy[16][68];
    int tid = threadIdx.x;
    {
        int row = tid >> 4, c4 = (tid & 15) * 4;
        float4 v = *reinterpret_cast<const float4*>(&g_y[b][head * 16 + row][sc * 64 + c4]);
        sy[row][c4] = v.x; sy[row][c4 + 1] = v.y;
        sy[row][c4 + 2] = v.z; sy[row][c4 + 3] = v.w;
    }
    __syncthreads();
    int i = tid >> 4, j = tid & 15;
    float a0 = 0.f, a1 = 0.f, a2 = 0.f, a3 = 0.f;
#pragma unroll
    for (int s = 0; s < 64; s += 4) {
        a0 += sy[i][s] * sy[j][s];
        a1 += sy[i][s + 1] * sy[j][s + 1];
        a2 += sy[i][s + 2] * sy[j][s + 2];
        a3 += sy[i][s + 3] * sy[j][s + 3];
    }
    g_gram[b][head][sc][i][j] = (a0 + a1) + (a2 + a3);
}

// ---------------------------------------------------------------------------
// K4: stats + combine Syy + channel attention (affine identity). grid=16.
// ---------------------------------------------------------------------------
__global__ void k4_attn(const float* __restrict__ gn, const float* __restrict__ btn,
                        const float* __restrict__ wq, const float* __restrict__ wk,
                        const float* __restrict__ wv) {
    pdl_wait();
    int b = blockIdx.x >> 3;
    int head = blockIdx.x & 7;
    int c0 = head * 16;
    int tid = threadIdx.x;
    __shared__ double rs[8], rq[8];
    __shared__ float stat[2];
    __shared__ float Syy[16][16];
    __shared__ float Sy[16];

    double s = 0.0, q = 0.0;
    for (int i = tid; i < 1024; i += 256) {
        s += g_part[b * 1024 + i][0];
        q += g_part[b * 1024 + i][1];
    }
#pragma unroll
    for (int o = 16; o; o >>= 1) {
        s += __shfl_down_sync(0xffffffffu, s, o);
        q += __shfl_down_sync(0xffffffffu, q, o);
    }
    if ((tid & 31) == 0) { rs[tid >> 5] = s; rq[tid >> 5] = q; }

    {
        int i = tid >> 4, j = tid & 15;
        float a = 0.f;
#pragma unroll
        for (int sc = 0; sc < 8; ++sc) a += g_gram[b][head][sc][i][j];
        Syy[i][j] = a;
    }
    if (tid < 16) {
        double a = 0.0;
#pragma unroll
        for (int dd = 0; dd < 8; ++dd) a += g_part[(b * 128 + c0 + tid) * 8 + dd][0];
        Sy[tid] = (float)a;
    }
    __syncthreads();
    if (tid == 0) {
        double S = 0.0, Q = 0.0;
        for (int i = 0; i < 8; ++i) { S += rs[i]; Q += rq[i]; }
        double n = (double)(CC * SLEN);
        double mu = S / n;
        double var = Q / n - mu * mu;
        stat[0] = (float)mu;
        stat[1] = (float)(1.0 / sqrt(var + 1e-5));
    }
    __syncthreads();

    if (tid < 16) {
        double mu = stat[0], rstd = stat[1];
        int i = tid;
        double ai = rstd * (double)gn[c0 + i];
        double bi = (double)btn[c0 + i] - mu * ai;
        double qi = (double)wq[c0 + i] * 0.25;  // includes HD^-0.5
        double sc_[16], vm[16];
        double m = -1e300;
#pragma unroll
        for (int j = 0; j < 16; ++j) {
            double aj = rstd * (double)gn[c0 + j];
            double bj = (double)btn[c0 + j] - mu * aj;
            double G = ai * aj * (double)Syy[i][j] + ai * bj * (double)Sy[i]
                     + bi * aj * (double)Sy[j] + 512.0 * bi * bj;
            sc_[j] = qi * (double)wk[c0 + j] * G;
            vm[j] = (double)wv[c0 + j] * (aj * (double)Sy[j] + 512.0 * bj) * (1.0 / 512.0);
            if (sc_[j] > m) m = sc_[j];
        }
        double sum = 0.0, o = 0.0;
#pragma unroll
        for (int j = 0; j < 16; ++j) {
            double e = exp(sc_[j] - m);
            sum += e;
            o += e * vm[j];
        }
        o /= sum;
        g_ca[b][c0 + i] = (float)(1.0 / (1.0 + exp(-o)));
    }
}

// ---------------------------------------------------------------------------
// K5: out = xh(fp16, L2-resident) * gd*gh*gw*ca. grid = 2048, blockDim 416,
// 3 blocks/SM. __ldcs reads (last use), __stcs writes; discard L2 region after.
// ---------------------------------------------------------------------------
__global__ void __launch_bounds__(416, 3) k5_gate_out(float* __restrict__ out) {
    pdl_wait();
    int id = blockIdx.x;
    int ch = id & 7;
    int bc = id >> 3;
    int b = bc >> 7, c = bc & 127;
    const uint2* xp = g_xh + (size_t)bc * SPQ;
    float4* op = reinterpret_cast<float4*>(out + (size_t)bc * SP);

    __shared__ float srs[392];
    __shared__ float4 sgw4[14];

    int t = threadIdx.x;
    bool act = t < 392;
    if (act) {
        int dl = t / 56, h = t % 56;
        srs[t] = g_gate[0][b][c][ch * 7 + dl] * g_gate[1][b][c][h] * g_ca[b][c];
    }
    if (t < 14) {
        sgw4[t] = reinterpret_cast<const float4*>(&g_gate[2][b][c][0])[t];
    }
    __syncthreads();

    if (act) {
        int q = t % 14, R0 = t / 14;
        float4 gw = sgw4[q];
        int base = ch * 5488 + R0 * 14 + q;
        uint2 u[7];
#pragma unroll
        for (int half = 0; half < 2; ++half) {
            int m0 = half * 7;
#pragma unroll
            for (int m = 0; m < 7; ++m) u[m] = __ldcs(&xp[base + (m0 + m) * 392]);
#pragma unroll
            for (int m = 0; m < 7; ++m) {
                float sc = srs[R0 + 28 * (m0 + m)];
                float4 v = h4_to_f4(u[m]);
                v.x *= sc * gw.x;
                v.y *= sc * gw.y;
                v.z *= sc * gw.z;
                v.w *= sc * gw.w;
                __stcs(&op[base + (m0 + m) * 392], v);
            }
        }
    }
    __syncthreads();
    // Discard this block's g_xh region: 343 lines of 128B, region aligned.
    {
        const char* rbase = reinterpret_cast<const char*>(xp + ch * 5488);
        for (int l = t; l < 343; l += 416) {
            asm volatile("discard.global.L2 [%0], 128;"
                         :: "l"(rbase + (size_t)l * 128) : "memory");
        }
    }
}

// ---------------------------------------------------------------------------
// Host: launches 2-6 use PDL so each launch overlaps the predecessor's
// teardown; griddepcontrol.wait at kernel entry preserves ordering.
// ---------------------------------------------------------------------------
template <typename F, typename... Args>
static inline void launch_pdl(F f, dim3 grid, dim3 block, Args... args) {
    cudaLaunchConfig_t cfg = {};
    cfg.gridDim = grid;
    cfg.blockDim = block;
    cfg.dynamicSmemBytes = 0;
    cudaLaunchAttribute at[1];
    at[0].id = cudaLaunchAttributeProgrammaticStreamSerialization;
    at[0].val.programmaticStreamSerializationAllowed = 1;
    cfg.attrs = at;
    cfg.numAttrs = 1;
    cudaLaunchKernelEx(&cfg, f, args...);
}

extern "C" void kernel_launch(void* const* d_in, const int* in_sizes, int n_in,
                              void* d_out, int out_size) {
    const float* x = (const float*)d_in[0];
    float* out = (float*)d_out;

    k1_axis_means<<<BB * CC * 8, 416>>>(x);
    launch_pdl(k2_gates, dim3(24), dim3(256),
        (const float*)d_in[1], (const float*)d_in[2],
        (const float*)d_in[3], (const float*)d_in[4],
        (const float*)d_in[5], (const float*)d_in[6],
        (const float*)d_in[7], (const float*)d_in[8],
        (const float*)d_in[9], (const float*)d_in[10],
        (const float*)d_in[11], (const float*)d_in[12],
        (const float*)d_in[13], (const float*)d_in[14]);
    launch_pdl(k3_pool, dim3(BB * CC * 4), dim3(416));
    launch_pdl(k3b_gram, dim3(BB * 64), dim3(256));
    launch_pdl(k4_attn, dim3(BB * 8), dim3(256),
        (const float*)d_in[15], (const float*)d_in[16],
        (const float*)d_in[17], (const float*)d_in[18],
        (const float*)d_in[19]);
    launch_pdl(k5_gate_out, dim3(BB * CC * 8), dim3(416), out);
}